// round 4
// baseline (speedup 1.0000x reference)
#include <cuda_runtime.h>

// SharpenedCosineSimilarity forward, fused.
//   y_denorm = conv3x3(x, w / (||w||_2 + eps + q2))
//   y        = y_denorm / (sqrt(box3x3(sum_c x^2) + eps) + q2)
//   out      = sigmoid(y) * (|y| + eps)^(p2)      p2=(p/10)^2, q2=(q/100)^2
//
// Shapes: B=32, Cin=128, Cout=256, H=W=64, K=3, stride=1, pad=1.

#define CIN  128
#define COUT 256
#define HH   64
#define WW   64
#define BB   32
#define TC   64    // couts per block
#define TH   16    // output rows per block
#define TW   16    // output cols per block
#define CK   8     // cin chunk per smem stage
#define EPSF 1e-12f

// ---------------- device scratch (no allocations allowed) ----------------
__device__ float g_wn[CIN * 9 * COUT];   // normalized weights, [cin*9][cout]
__device__ float g_psqr[COUT];           // (p/10)^2
__device__ float g_s[BB * HH * WW];      // per-pixel sum_c x^2
__device__ float g_invden[BB * HH * WW]; // 1 / (sqrt(box3x3(s)+eps) + q2)

// ---------------- f32x2 helpers (Blackwell packed fp32) ----------------
static __device__ __forceinline__ unsigned long long pk2(float a, float b) {
    unsigned long long r;
    asm("mov.b64 %0, {%1, %2};" : "=l"(r) : "f"(a), "f"(b));
    return r;
}
static __device__ __forceinline__ void upk2(unsigned long long v, float& a, float& b) {
    asm("mov.b64 {%0, %1}, %2;" : "=f"(a), "=f"(b) : "l"(v));
}
static __device__ __forceinline__ void fma2(unsigned long long& d,
                                            unsigned long long a,
                                            unsigned long long b) {
    asm("fma.rn.f32x2 %0, %1, %2, %0;" : "+l"(d) : "l"(a), "l"(b));
}

// ---------------- prep kernels ----------------
__global__ void prep_w(const float* __restrict__ w,
                       const float* __restrict__ p,
                       const float* __restrict__ q) {
    __shared__ float red[4];
    const int co = blockIdx.x;
    const int tid = threadIdx.x;
    const float* wr = w + co * 1152;  // [Cout][Cin*3*3]

    float ssum = 0.f;
    for (int i = tid; i < 1152; i += 128) { float v = wr[i]; ssum += v * v; }
    #pragma unroll
    for (int o = 16; o; o >>= 1) ssum += __shfl_xor_sync(0xffffffff, ssum, o);
    if ((tid & 31) == 0) red[tid >> 5] = ssum;
    __syncthreads();
    const float tot = red[0] + red[1] + red[2] + red[3];

    const float qv = q[0] * 0.01f;
    const float qs = qv * qv;
    const float scale = 1.f / (sqrtf(tot) + EPSF + qs);

    // transpose to [cin*9][cout] for vectorized staging in the conv kernel
    for (int i = tid; i < 1152; i += 128)
        g_wn[i * COUT + co] = wr[i] * scale;

    if (tid == 0) { const float pv = p[co] * 0.1f; g_psqr[co] = pv * pv; }
}

__global__ void prep_s(const float* __restrict__ x) {
    const int i = blockIdx.x * 256 + threadIdx.x;  // < B*H*W
    const int b = i >> 12;
    const int hw = i & 4095;
    const float* xp = x + (size_t)b * CIN * 4096 + hw;
    float ssum = 0.f;
    #pragma unroll 8
    for (int c = 0; c < CIN; ++c) { float v = xp[c * 4096]; ssum += v * v; }
    g_s[i] = ssum;
}

__global__ void prep_invden(const float* __restrict__ q) {
    const int i = blockIdx.x * 256 + threadIdx.x;
    const int b = i >> 12;
    const int hw = i & 4095;
    const int h = hw >> 6, w = hw & 63;
    const float* sp = g_s + b * 4096;
    float acc = 0.f;
    #pragma unroll
    for (int dh = -1; dh <= 1; ++dh) {
        const int hh = h + dh;
        if ((unsigned)hh >= (unsigned)HH) continue;
        #pragma unroll
        for (int dw = -1; dw <= 1; ++dw) {
            const int ww2 = w + dw;
            if ((unsigned)ww2 >= (unsigned)WW) continue;
            acc += sp[hh * 64 + ww2];
        }
    }
    const float qv = q[0] * 0.01f;
    const float qs = qv * qv;
    g_invden[i] = 1.f / (sqrtf(acc + EPSF) + qs);
}

// ---------------- fused conv + epilogue ----------------
static __device__ __forceinline__ float scs_act(float y, float psqr) {
    const float sg = 1.f / (1.f + __expf(-y));
    const float mag = exp2f(psqr * __log2f(fabsf(y) + EPSF));
    return sg * mag;
}

// smem union: per-chunk buffers (CK*324 + CK*576 = 7200 floats) vs
// epilogue staging buffer (32*256 = 8192 floats) -> 8192 floats = 32KB static.
#define SMEM_FLOATS 8192

__global__ void __launch_bounds__(256, 2)
conv_kernel(const float* __restrict__ x, float* __restrict__ out) {
    __shared__ float smem[SMEM_FLOATS];
    float* sIn = smem;              // [CK][18][18]
    float* sW  = smem + CK * 324;   // [CK][9][64]

    const int tid = threadIdx.x;
    const int b   = blockIdx.z;
    const int co0 = blockIdx.y * TC;
    const int h0  = (blockIdx.x >> 2) * TH;
    const int w0g = (blockIdx.x & 3) * TW;

    const int cg    = tid >> 5;        // channel group 0..7 (8 couts each)
    const int s     = tid & 31;
    const int row   = s >> 1;          // output row 0..15
    const int wbase = (s & 1) * 8;     // output col base: 0 or 8

    unsigned long long acc[4][8];      // [channel-pair][pixel]
    #pragma unroll
    for (int i = 0; i < 4; ++i)
        #pragma unroll
        for (int j = 0; j < 8; ++j) acc[i][j] = 0ull;

    #pragma unroll 1
    for (int cb = 0; cb < CIN; cb += CK) {
        // ---- stage input tile (with halo, zero-padded) ----
        for (int idx = tid; idx < CK * 324; idx += 256) {
            const int cin = idx / 324;
            const int rem = idx - cin * 324;
            const int r = rem / 18, c = rem - r * 18;
            const int gh = h0 - 1 + r, gw = w0g - 1 + c;
            float v = 0.f;
            if ((unsigned)gh < (unsigned)HH && (unsigned)gw < (unsigned)WW)
                v = x[(((size_t)b * CIN + cb + cin) * HH + gh) * WW + gw];
            sIn[idx] = v;
        }
        // ---- stage weights: [CK][9][64 couts] via float4 ----
        for (int idx = tid; idx < CK * 9 * 16; idx += 256) {
            const int v = idx >> 4;             // (cin*9 + kk)
            const int off = (idx & 15) * 4;     // cout offset within tile
            const float4 w4 =
                *(const float4*)&g_wn[(size_t)(cb * 9 + v) * COUT + co0 + off];
            *(float4*)&sW[v * 64 + off] = w4;
        }
        __syncthreads();

        // ---- compute ----
        #pragma unroll 1
        for (int cin = 0; cin < CK; ++cin) {
            #pragma unroll
            for (int kh = 0; kh < 3; ++kh) {
                const float* ir = &sIn[cin * 324 + (row + kh) * 18 + wbase];
                unsigned long long xd[10];
                #pragma unroll
                for (int j = 0; j < 10; ++j) { const float t = ir[j]; xd[j] = pk2(t, t); }
                const float* wr = &sW[(cin * 9 + kh * 3) * 64 + cg * 8];
                #pragma unroll
                for (int kw = 0; kw < 3; ++kw) {
                    const float4 wa = *(const float4*)(wr + kw * 64);
                    const float4 wb = *(const float4*)(wr + kw * 64 + 4);
                    const unsigned long long wp0 = pk2(wa.x, wa.y);
                    const unsigned long long wp1 = pk2(wa.z, wa.w);
                    const unsigned long long wp2 = pk2(wb.x, wb.y);
                    const unsigned long long wp3 = pk2(wb.z, wb.w);
                    #pragma unroll
                    for (int j = 0; j < 8; ++j) {
                        fma2(acc[0][j], wp0, xd[kw + j]);
                        fma2(acc[1][j], wp1, xd[kw + j]);
                        fma2(acc[2][j], wp2, xd[kw + j]);
                        fma2(acc[3][j], wp3, xd[kw + j]);
                    }
                }
            }
        }
        __syncthreads();
    }

    // ---- epilogue: normalize, activate, stage through smem, coalesced store ----
    float invd[8];
    #pragma unroll
    for (int j = 0; j < 8; ++j)
        invd[j] = g_invden[((size_t)b * HH + h0 + row) * WW + w0g + wbase + j];
    float ps[8];
    #pragma unroll
    for (int cc = 0; cc < 8; ++cc) ps[cc] = g_psqr[co0 + cg * 8 + cc];

    float* stage = smem;  // 8192 floats = [32 ch][256 px]
    #pragma unroll 1
    for (int pass = 0; pass < 2; ++pass) {
        __syncthreads();
        if ((cg >> 2) == pass) {
            const int lcb = (cg & 3) * 8;  // local channel base within 32
            #pragma unroll
            for (int cp = 0; cp < 4; ++cp) {
                #pragma unroll
                for (int j = 0; j < 8; ++j) {
                    float a0, a1;
                    upk2(acc[cp][j], a0, a1);
                    const float y0 = a0 * invd[j];
                    const float y1 = a1 * invd[j];
                    const int sp = row * 16 + wbase + j;
                    stage[(lcb + cp * 2 + 0) * 256 + sp] = scs_act(y0, ps[cp * 2 + 0]);
                    stage[(lcb + cp * 2 + 1) * 256 + sp] = scs_act(y1, ps[cp * 2 + 1]);
                }
            }
        }
        __syncthreads();
        for (int idx = tid; idx < 32 * 256; idx += 256) {
            const int ch = idx >> 8;
            const int sp = idx & 255;
            const int r = sp >> 4, w = sp & 15;
            const int co = co0 + pass * 32 + ch;
            out[(((size_t)b * COUT + co) * HH + h0 + r) * WW + w0g + w] = stage[idx];
        }
    }
}

// ---------------- launch ----------------
extern "C" void kernel_launch(void* const* d_in, const int* in_sizes, int n_in,
                              void* d_out, int out_size) {
    const float *x = nullptr, *w = nullptr, *p = nullptr, *q = nullptr;
    for (int i = 0; i < n_in; ++i) {
        const int sz = in_sizes[i];
        if (sz == BB * CIN * HH * WW)      x = (const float*)d_in[i];
        else if (sz == COUT * CIN * 9)     w = (const float*)d_in[i];
        else if (sz == COUT)               p = (const float*)d_in[i];
        else if (sz == 1)                  q = (const float*)d_in[i];
    }
    float* out = (float*)d_out;

    prep_w<<<COUT, 128>>>(w, p, q);
    prep_s<<<(BB * HH * WW) / 256, 256>>>(x);
    prep_invden<<<(BB * HH * WW) / 256, 256>>>(q);

    dim3 grid(16, 4, 32);  // (4x4 spatial tiles, 4 cout tiles, 32 images)
    conv_kernel<<<grid, 256>>>(x, out);
}

// round 6
// speedup vs baseline: 1.4517x; 1.4517x over previous
#include <cuda_runtime.h>
#include <cuda_bf16.h>
#include <cstdint>

// SharpenedCosineSimilarity forward via mma.sync bf16 hi/lo split GEMM.
// (tcgen05 is unavailable: harness compiles at .target sm_103, not sm_103a.)
// GEMM view: M=Cout=256, N=B*H*W=131072, K=Cin*9=1152.

#define CIN   128
#define COUT  256
#define HH    64
#define WW    64
#define BB    32
#define KTOT  1152
#define NTOT  (BB*HH*WW)
#define EPSF  1e-12f

#define MT    128
#define NT    128
#define KC    32
#define NKIT  (KTOT/KC)      // 36

#define KROW  40             // bf16 per smem row: 32 data + 8 pad
#define ROWB  80             // bytes per smem row (conflict-free for ldmatrix)
#define TILEB (128*ROWB)     // one 128-row tile = 10240 B
#define STAGE_BYTES (4*TILEB) // Ahi|Alo|Bhi|Blo = 40960 B
#define SMEM_TOTAL  (2*STAGE_BYTES)

// ---------------- device scratch (static; no allocations) ----------------
__device__ __nv_bfloat16 g_Ahi[COUT * KTOT];
__device__ __nv_bfloat16 g_Alo[COUT * KTOT];
__device__ __nv_bfloat16 g_Bhi[(size_t)NTOT * KTOT];   // ~302MB
__device__ __nv_bfloat16 g_Blo[(size_t)NTOT * KTOT];   // ~302MB
__device__ float g_psqr[COUT];
__device__ float g_s[NTOT];
__device__ float g_invden[NTOT];

// ---------------- PTX helpers (sm_80-level features only) ----------------
static __device__ __forceinline__ uint32_t smem_u32(const void* p) {
    uint32_t a;
    asm("{ .reg .u64 t; cvta.to.shared.u64 t, %1; cvt.u32.u64 %0, t; }" : "=r"(a) : "l"(p));
    return a;
}
#define CP_ASYNC16(s, g) \
    asm volatile("cp.async.cg.shared.global [%0], [%1], 16;" :: "r"(s), "l"(g) : "memory")
#define CP_COMMIT()  asm volatile("cp.async.commit_group;" ::: "memory")
#define CP_WAIT(n)   asm volatile("cp.async.wait_group %0;" :: "n"(n) : "memory")

#define LDSM4(r0, r1, r2, r3, a) \
    asm volatile("ldmatrix.sync.aligned.m8n8.x4.shared.b16 {%0,%1,%2,%3}, [%4];" \
        : "=r"(r0), "=r"(r1), "=r"(r2), "=r"(r3) : "r"(a))

static __device__ __forceinline__ void mma_bf16(float* d, const uint32_t* a,
                                                uint32_t b0, uint32_t b1) {
    asm volatile(
        "mma.sync.aligned.m16n8k16.row.col.f32.bf16.bf16.f32 "
        "{%0,%1,%2,%3}, {%4,%5,%6,%7}, {%8,%9}, {%0,%1,%2,%3};"
        : "+f"(d[0]), "+f"(d[1]), "+f"(d[2]), "+f"(d[3])
        : "r"(a[0]), "r"(a[1]), "r"(a[2]), "r"(a[3]), "r"(b0), "r"(b1));
}

// ---------------- prep kernels ----------------
__global__ void prep_w(const float* __restrict__ w,
                       const float* __restrict__ p,
                       const float* __restrict__ q) {
    __shared__ float red[4];
    const int co = blockIdx.x;
    const int tid = threadIdx.x;  // 128
    const float* wr = w + co * KTOT;
    float ssum = 0.f;
    for (int i = tid; i < KTOT; i += 128) { const float v = wr[i]; ssum += v * v; }
    #pragma unroll
    for (int o = 16; o; o >>= 1) ssum += __shfl_xor_sync(0xffffffff, ssum, o);
    if ((tid & 31) == 0) red[tid >> 5] = ssum;
    __syncthreads();
    const float tot = red[0] + red[1] + red[2] + red[3];
    const float qv = q[0] * 0.01f;
    const float qs = qv * qv;
    const float scale = 1.f / (sqrtf(tot) + EPSF + qs);
    for (int i = tid; i < KTOT; i += 128) {
        const float v = wr[i] * scale;
        const __nv_bfloat16 hi = __float2bfloat16(v);
        g_Ahi[co * KTOT + i] = hi;
        g_Alo[co * KTOT + i] = __float2bfloat16(v - __bfloat162float(hi));
    }
    if (tid == 0) { const float pv = p[co] * 0.1f; g_psqr[co] = pv * pv; }
}

__global__ void prep_s(const float* __restrict__ x) {
    const int i = blockIdx.x * 256 + threadIdx.x;
    const int b = i >> 12;
    const int hw = i & 4095;
    const float* xp = x + (size_t)b * CIN * 4096 + hw;
    float ssum = 0.f;
    #pragma unroll 8
    for (int c = 0; c < CIN; ++c) { const float v = xp[c * 4096]; ssum += v * v; }
    g_s[i] = ssum;
}

__global__ void prep_invden(const float* __restrict__ q) {
    const int i = blockIdx.x * 256 + threadIdx.x;
    const int b = i >> 12;
    const int hw = i & 4095;
    const int h = hw >> 6, w = hw & 63;
    const float* sp = g_s + b * 4096;
    float acc = 0.f;
    #pragma unroll
    for (int dh = -1; dh <= 1; ++dh) {
        const int hh = h + dh;
        if ((unsigned)hh >= (unsigned)HH) continue;
        #pragma unroll
        for (int dw = -1; dw <= 1; ++dw) {
            const int w2 = w + dw;
            if ((unsigned)w2 >= (unsigned)WW) continue;
            acc += sp[hh * 64 + w2];
        }
    }
    const float qv = q[0] * 0.01f;
    const float qs = qv * qv;
    g_invden[i] = 1.f / (sqrtf(acc + EPSF) + qs);
}

// im2col: B[n][k] = x[b][cin][h+kh-1][w+kw-1], split bf16 hi/lo.
__global__ void __launch_bounds__(256)
prep_im2col(const float* __restrict__ x) {
    __shared__ float xs[16 * 4 * 64];
    const int blk = blockIdx.x;
    const int b = blk >> 5;
    const int h0 = (blk & 31) * 2;
    const int tid = threadIdx.x;

    #pragma unroll 1
    for (int cb = 0; cb < CIN; cb += 16) {
        for (int i = tid; i < 16 * 4 * 64; i += 256) {
            const int c = i >> 8;
            const int r = (i >> 6) & 3;
            const int w = i & 63;
            const int hh = h0 - 1 + r;
            float v = 0.f;
            if ((unsigned)hh < (unsigned)HH)
                v = x[(((size_t)b * CIN + cb + c) * HH + hh) * WW + w];
            xs[i] = v;
        }
        __syncthreads();
        for (int idx = tid; idx < 128 * 144; idx += 256) {
            const int nl = idx / 144;
            const int kk = idx - nl * 144;
            const int cl = kk / 9;
            const int t = kk - cl * 9;
            const int dh = t / 3;
            const int dw = t - dh * 3;
            const int rl = nl >> 6;
            const int w = (nl & 63) + dw - 1;
            float v = 0.f;
            if ((unsigned)w < (unsigned)WW)
                v = xs[(cl << 8) + ((rl + dh) << 6) + w];
            const __nv_bfloat16 hi = __float2bfloat16(v);
            const __nv_bfloat16 lo = __float2bfloat16(v - __bfloat162float(hi));
            const size_t n = (size_t)b * 4096 + (h0 + rl) * 64 + (nl & 63);
            const size_t off = n * KTOT + cb * 9 + kk;
            g_Bhi[off] = hi;
            g_Blo[off] = lo;
        }
        __syncthreads();
    }
}

// ---------------- GEMM + fused epilogue ----------------
static __device__ __forceinline__ float scs_act(float y, float psqr) {
    const float sg = __fdividef(1.f, 1.f + __expf(-y));
    const float mag = exp2f(psqr * __log2f(fabsf(y) + EPSF));
    return sg * mag;
}

static __device__ __forceinline__ void stage_load(uint32_t sb, int m0, int n0,
                                                  int k0, int tid) {
    #pragma unroll
    for (int rep = 0; rep < 8; ++rep) {
        const int idx = rep * 256 + tid;
        const int c   = idx & 3;
        const int row = (idx >> 2) & 127;
        const int arr = (idx >> 9) & 1;
        const int ab  = idx >> 10;  // 0 = A, 1 = B
        const uint32_t sa = sb + ab * (2 * TILEB) + arr * TILEB + row * ROWB + c * 16;
        const char* g;
        if (ab == 0)
            g = (const char*)(arr ? g_Alo : g_Ahi)
              + ((size_t)(m0 + row) * KTOT + k0) * 2 + c * 16;
        else
            g = (const char*)(arr ? g_Blo : g_Bhi)
              + ((size_t)(n0 + row) * KTOT + k0) * 2 + c * 16;
        CP_ASYNC16(sa, g);
    }
    CP_COMMIT();
}

__global__ void __launch_bounds__(256, 2)
conv_mma(float* __restrict__ out) {
    extern __shared__ char smem[];
    const uint32_t sbase = smem_u32(smem);
    const int tid = threadIdx.x;
    const int lane = tid & 31;
    const int wid = tid >> 5;
    const int warp_m = wid >> 2;    // 0..1
    const int warp_n = wid & 3;     // 0..3
    const int m0 = blockIdx.x * MT;
    const int n0 = blockIdx.y * NT;

    float acc[4][4][4];
    #pragma unroll
    for (int i = 0; i < 4; ++i)
        #pragma unroll
        for (int j = 0; j < 4; ++j)
            #pragma unroll
            for (int k = 0; k < 4; ++k) acc[i][j][k] = 0.f;

    stage_load(sbase, m0, n0, 0, tid);
    stage_load(sbase + STAGE_BYTES, m0, n0, KC, tid);

    const int lrow = lane & 15;
    const int lkg  = lane >> 4;

    #pragma unroll 1
    for (int kit = 0; kit < NKIT; ++kit) {
        if (kit < NKIT - 2) CP_WAIT(1); else CP_WAIT(0);
        __syncthreads();
        const uint32_t sb = sbase + (kit & 1) * STAGE_BYTES;
        const uint32_t sBh = sb + 2 * TILEB;
        const uint32_t sBl = sb + 3 * TILEB;

        #pragma unroll
        for (int ks = 0; ks < 2; ++ks) {
            const uint32_t kb = ks * 32 + lkg * 16;
            uint32_t bh[2][4], bl[2][4];
            #pragma unroll
            for (int np = 0; np < 2; ++np) {
                const uint32_t boff = (warp_n * 32 + np * 16 + lrow) * ROWB + kb;
                LDSM4(bh[np][0], bh[np][1], bh[np][2], bh[np][3], sBh + boff);
                LDSM4(bl[np][0], bl[np][1], bl[np][2], bl[np][3], sBl + boff);
            }
            #pragma unroll
            for (int ma = 0; ma < 4; ++ma) {
                const uint32_t aoff = (warp_m * 64 + ma * 16 + lrow) * ROWB + kb;
                uint32_t ah[4], al[4];
                LDSM4(ah[0], ah[1], ah[2], ah[3], sb + aoff);
                LDSM4(al[0], al[1], al[2], al[3], sb + TILEB + aoff);
                #pragma unroll
                for (int na = 0; na < 4; ++na) {
                    const int np = na >> 1;
                    const int hi = na & 1;  // 0: {r0,r2}, 1: {r1,r3}
                    const uint32_t b0h = bh[np][hi], b1h = bh[np][hi + 2];
                    const uint32_t b0l = bl[np][hi], b1l = bl[np][hi + 2];
                    mma_bf16(acc[ma][na], ah, b0h, b1h);
                    mma_bf16(acc[ma][na], ah, b0l, b1l);
                    mma_bf16(acc[ma][na], al, b0h, b1h);
                }
            }
        }
        __syncthreads();
        if (kit + 2 < NKIT)
            stage_load(sbase + (kit & 1) * STAGE_BYTES, m0, n0, (kit + 2) * KC, tid);
    }

    // ---- epilogue ----
    const int b = n0 >> 12;
    const int hwbase = n0 & 4095;
    #pragma unroll
    for (int ma = 0; ma < 4; ++ma) {
        const int mrow = warp_m * 64 + ma * 16 + (lane >> 2);
        #pragma unroll
        for (int na = 0; na < 4; ++na) {
            const int nloc = warp_n * 32 + na * 8 + 2 * (lane & 3);
            const float2 inv = *(const float2*)&g_invden[n0 + nloc];
            #pragma unroll
            for (int h = 0; h < 2; ++h) {
                const int co = m0 + mrow + h * 8;
                const float psqr = g_psqr[co];
                float2 o2;
                o2.x = scs_act(acc[ma][na][h * 2 + 0] * inv.x, psqr);
                o2.y = scs_act(acc[ma][na][h * 2 + 1] * inv.y, psqr);
                *(float2*)&out[(((size_t)b * COUT + co) << 12) + hwbase + nloc] = o2;
            }
        }
    }
}

// ---------------- launch ----------------
extern "C" void kernel_launch(void* const* d_in, const int* in_sizes, int n_in,
                              void* d_out, int out_size) {
    const float *x = nullptr, *w = nullptr, *p = nullptr, *q = nullptr;
    for (int i = 0; i < n_in; ++i) {
        const int sz = in_sizes[i];
        if (sz == BB * CIN * HH * WW)      x = (const float*)d_in[i];
        else if (sz == COUT * CIN * 9)     w = (const float*)d_in[i];
        else if (sz == COUT)               p = (const float*)d_in[i];
        else if (sz == 1)                  q = (const float*)d_in[i];
    }
    float* out = (float*)d_out;

    cudaFuncSetAttribute(conv_mma, cudaFuncAttributeMaxDynamicSharedMemorySize,
                         SMEM_TOTAL);

    prep_w<<<COUT, 128>>>(w, p, q);
    prep_s<<<NTOT / 256, 256>>>(x);
    prep_invden<<<NTOT / 256, 256>>>(q);
    prep_im2col<<<1024, 256>>>(x);

    dim3 grid(2, NTOT / NT);  // M fastest: both M-tiles of an N-tile adjacent (L2 reuse of B)
    conv_mma<<<grid, 256, SMEM_TOTAL>>>(out);
}

// round 7
// speedup vs baseline: 1.9442x; 1.3392x over previous
#include <cuda_runtime.h>
#include <cuda_bf16.h>
#include <cstdint>

// SharpenedCosineSimilarity forward via mma.sync bf16 hi/lo split GEMM with
// IMPLICIT im2col (K reordered as k = tap*128 + cin; B tiles staged straight
// from a channel-last bf16 hi/lo copy of x with cp.async zero-fill halos).
// GEMM view: M=Cout=256, N=B*H*W=131072, K=Cin*9=1152.

#define CIN   128
#define COUT  256
#define HH    64
#define WW    64
#define BB    32
#define KTOT  1152
#define NTOT  (BB*HH*WW)
#define EPSF  1e-12f

#define MT    128
#define NT    128
#define KC    32
#define NKIT  (KTOT/KC)      // 36

#define ROWB  80             // bytes per smem row: 64 data + 16 pad (conflict-free ldmatrix)
#define TILEB (128*ROWB)     // one 128-row tile = 10240 B
#define STAGE_BYTES (4*TILEB) // Ahi|Alo|Bhi|Blo = 40960 B
#define SMEM_TOTAL  (2*STAGE_BYTES)

// ---------------- device scratch (static; no allocations) ----------------
__device__ __nv_bfloat16 g_Ahi[COUT * KTOT];          // weights, k = tap*128+cin
__device__ __nv_bfloat16 g_Alo[COUT * KTOT];
__device__ __nv_bfloat16 g_xhi[(size_t)NTOT * CIN];   // channel-last x hi (33.5MB)
__device__ __nv_bfloat16 g_xlo[(size_t)NTOT * CIN];   // channel-last x lo
__device__ float g_psqr[COUT];
__device__ float g_s[NTOT];
__device__ float g_invden[NTOT];

// ---------------- PTX helpers (sm_80-level features only) ----------------
static __device__ __forceinline__ uint32_t smem_u32(const void* p) {
    uint32_t a;
    asm("{ .reg .u64 t; cvta.to.shared.u64 t, %1; cvt.u32.u64 %0, t; }" : "=r"(a) : "l"(p));
    return a;
}
#define CP_ASYNC16(s, g) \
    asm volatile("cp.async.cg.shared.global [%0], [%1], 16;" :: "r"(s), "l"(g) : "memory")
#define CP_ASYNC16_Z(s, g, sz) \
    asm volatile("cp.async.cg.shared.global [%0], [%1], 16, %2;" :: "r"(s), "l"(g), "r"(sz) : "memory")
#define CP_COMMIT()  asm volatile("cp.async.commit_group;" ::: "memory")
#define CP_WAIT(n)   asm volatile("cp.async.wait_group %0;" :: "n"(n) : "memory")

#define LDSM4(r0, r1, r2, r3, a) \
    asm volatile("ldmatrix.sync.aligned.m8n8.x4.shared.b16 {%0,%1,%2,%3}, [%4];" \
        : "=r"(r0), "=r"(r1), "=r"(r2), "=r"(r3) : "r"(a))

static __device__ __forceinline__ void mma_bf16(float* d, const uint32_t* a,
                                                uint32_t b0, uint32_t b1) {
    asm volatile(
        "mma.sync.aligned.m16n8k16.row.col.f32.bf16.bf16.f32 "
        "{%0,%1,%2,%3}, {%4,%5,%6,%7}, {%8,%9}, {%0,%1,%2,%3};"
        : "+f"(d[0]), "+f"(d[1]), "+f"(d[2]), "+f"(d[3])
        : "r"(a[0]), "r"(a[1]), "r"(a[2]), "r"(a[3]), "r"(b0), "r"(b1));
}

// ---------------- prep kernels ----------------
__global__ void prep_w(const float* __restrict__ w,
                       const float* __restrict__ p,
                       const float* __restrict__ q) {
    __shared__ float red[4];
    const int co = blockIdx.x;
    const int tid = threadIdx.x;  // 128
    const float* wr = w + co * KTOT;  // layout [Cin][3][3] per cout
    float ssum = 0.f;
    for (int i = tid; i < KTOT; i += 128) { const float v = wr[i]; ssum += v * v; }
    #pragma unroll
    for (int o = 16; o; o >>= 1) ssum += __shfl_xor_sync(0xffffffff, ssum, o);
    if ((tid & 31) == 0) red[tid >> 5] = ssum;
    __syncthreads();
    const float tot = red[0] + red[1] + red[2] + red[3];
    const float qv = q[0] * 0.01f;
    const float qs = qv * qv;
    const float scale = 1.f / (sqrtf(tot) + EPSF + qs);
    for (int i = tid; i < KTOT; i += 128) {
        const int cin = i / 9;
        const int t = i - cin * 9;
        const int k = t * 128 + cin;     // reordered K axis
        const float v = wr[i] * scale;
        const __nv_bfloat16 hi = __float2bfloat16(v);
        g_Ahi[co * KTOT + k] = hi;
        g_Alo[co * KTOT + k] = __float2bfloat16(v - __bfloat162float(hi));
    }
    if (tid == 0) { const float pv = p[co] * 0.1f; g_psqr[co] = pv * pv; }
}

// x[b][cin][h][w] -> xT[b][h][w][cin] split to bf16 hi/lo. 32x32 tiled transpose.
__global__ void __launch_bounds__(256)
prep_split(const float* __restrict__ x) {
    __shared__ float xs[32][33];
    const int b  = blockIdx.z;
    const int c0 = blockIdx.y * 32;
    const int p0 = blockIdx.x * 32;   // hw tile base
    const int tx = threadIdx.x & 31, ty = threadIdx.x >> 5;  // 32 x 8

    #pragma unroll
    for (int i = 0; i < 4; ++i) {
        const int c = ty + i * 8;
        xs[c][tx] = x[((size_t)b * CIN + c0 + c) * 4096 + p0 + tx];
    }
    __syncthreads();

    const int p  = threadIdx.x >> 3;       // pixel within tile
    const int g4 = (threadIdx.x & 7) * 4;  // cin group of 4
    uint2 hi, lo;
    __nv_bfloat16* ph = (__nv_bfloat16*)&hi;
    __nv_bfloat16* pl = (__nv_bfloat16*)&lo;
    #pragma unroll
    for (int j = 0; j < 4; ++j) {
        const float v = xs[g4 + j][p];
        const __nv_bfloat16 h = __float2bfloat16(v);
        ph[j] = h;
        pl[j] = __float2bfloat16(v - __bfloat162float(h));
    }
    const size_t o = ((size_t)b * 4096 + p0 + p) * CIN + c0 + g4;
    *(uint2*)((char*)g_xhi + o * 2) = hi;
    *(uint2*)((char*)g_xlo + o * 2) = lo;
}

__global__ void prep_s(const float* __restrict__ x) {
    const int i = blockIdx.x * 256 + threadIdx.x;
    const int b = i >> 12;
    const int hw = i & 4095;
    const float* xp = x + (size_t)b * CIN * 4096 + hw;
    float ssum = 0.f;
    #pragma unroll 8
    for (int c = 0; c < CIN; ++c) { const float v = xp[c * 4096]; ssum += v * v; }
    g_s[i] = ssum;
}

__global__ void prep_invden(const float* __restrict__ q) {
    const int i = blockIdx.x * 256 + threadIdx.x;
    const int b = i >> 12;
    const int hw = i & 4095;
    const int h = hw >> 6, w = hw & 63;
    const float* sp = g_s + b * 4096;
    float acc = 0.f;
    #pragma unroll
    for (int dh = -1; dh <= 1; ++dh) {
        const int hh = h + dh;
        if ((unsigned)hh >= (unsigned)HH) continue;
        #pragma unroll
        for (int dw = -1; dw <= 1; ++dw) {
            const int w2 = w + dw;
            if ((unsigned)w2 >= (unsigned)WW) continue;
            acc += sp[hh * 64 + w2];
        }
    }
    const float qv = q[0] * 0.01f;
    const float qs = qv * qv;
    g_invden[i] = 1.f / (sqrtf(acc + EPSF) + qs);
}

// ---------------- GEMM + fused epilogue ----------------
static __device__ __forceinline__ float scs_act(float y, float psqr) {
    const float sg = __fdividef(1.f, 1.f + __expf(-y));
    const float mag = exp2f(psqr * __log2f(fabsf(y) + EPSF));
    return sg * mag;
}

// Stage one KC=32 chunk: A from reordered weights, B implicitly from xT
// (tap-shifted window, zero-filled halo via cp.async src-size).
static __device__ __forceinline__ void stage_load(uint32_t sb, int m0, int n0,
                                                  int kit, int tid) {
    const int k0 = kit * KC;
    // ---- A: 2 arrays x 128 rows x 4 x 16B ----
    #pragma unroll
    for (int rep = 0; rep < 4; ++rep) {
        const int idx = rep * 256 + tid;
        const int c   = idx & 3;
        const int row = (idx >> 2) & 127;
        const int arr = idx >> 9;
        const uint32_t sa = sb + arr * TILEB + row * ROWB + c * 16;
        const char* g = (const char*)(arr ? g_Alo : g_Ahi)
                      + ((size_t)(m0 + row) * KTOT + k0) * 2 + c * 16;
        CP_ASYNC16(sa, g);
    }
    // ---- B: implicit im2col from xT ----
    const int t    = kit >> 2;          // tap 0..8
    const int cinb = (kit & 3) * 32;    // cin block
    const int dh = t / 3 - 1;
    const int dw = t - (t / 3) * 3 - 1;
    const int b  = n0 >> 12;
    const int h0 = (n0 & 4095) >> 6;    // first of 2 output rows
    #pragma unroll
    for (int rep = 0; rep < 4; ++rep) {
        const int idx = rep * 256 + tid;
        const int c   = idx & 3;
        const int row = (idx >> 2) & 127;  // pixel within tile
        const int arr = idx >> 9;
        const uint32_t sa = sb + (2 + arr) * TILEB + row * ROWB + c * 16;
        const int h = h0 + (row >> 6) + dh;
        const int w = (row & 63) + dw;
        const bool ok = ((unsigned)h < (unsigned)HH) && ((unsigned)w < (unsigned)WW);
        const int hc = ok ? h : 0;
        const int wc = ok ? w : 0;
        const size_t off =
            (((size_t)b * 4096 + hc * 64 + wc) * CIN + cinb + c * 8) * 2;
        const char* g = (const char*)(arr ? g_xlo : g_xhi) + off;
        const int sz = ok ? 16 : 0;
        CP_ASYNC16_Z(sa, g, sz);
    }
    CP_COMMIT();
}

__global__ void __launch_bounds__(256, 2)
conv_mma(float* __restrict__ out) {
    extern __shared__ char smem[];
    const uint32_t sbase = smem_u32(smem);
    const int tid = threadIdx.x;
    const int lane = tid & 31;
    const int wid = tid >> 5;
    const int warp_m = wid >> 2;    // 0..1
    const int warp_n = wid & 3;     // 0..3
    const int m0 = blockIdx.x * MT;
    const int n0 = blockIdx.y * NT;

    float acc[4][4][4];
    #pragma unroll
    for (int i = 0; i < 4; ++i)
        #pragma unroll
        for (int j = 0; j < 4; ++j)
            #pragma unroll
            for (int k = 0; k < 4; ++k) acc[i][j][k] = 0.f;

    stage_load(sbase, m0, n0, 0, tid);
    stage_load(sbase + STAGE_BYTES, m0, n0, 1, tid);

    const int lrow = lane & 15;
    const int lkg  = lane >> 4;

    #pragma unroll 1
    for (int kit = 0; kit < NKIT; ++kit) {
        if (kit < NKIT - 2) CP_WAIT(1); else CP_WAIT(0);
        __syncthreads();
        const uint32_t sb = sbase + (kit & 1) * STAGE_BYTES;
        const uint32_t sBh = sb + 2 * TILEB;
        const uint32_t sBl = sb + 3 * TILEB;

        #pragma unroll
        for (int ks = 0; ks < 2; ++ks) {
            const uint32_t kb = ks * 32 + lkg * 16;
            uint32_t bh[2][4], bl[2][4];
            #pragma unroll
            for (int np = 0; np < 2; ++np) {
                const uint32_t boff = (warp_n * 32 + np * 16 + lrow) * ROWB + kb;
                LDSM4(bh[np][0], bh[np][1], bh[np][2], bh[np][3], sBh + boff);
                LDSM4(bl[np][0], bl[np][1], bl[np][2], bl[np][3], sBl + boff);
            }
            #pragma unroll
            for (int ma = 0; ma < 4; ++ma) {
                const uint32_t aoff = (warp_m * 64 + ma * 16 + lrow) * ROWB + kb;
                uint32_t ah[4], al[4];
                LDSM4(ah[0], ah[1], ah[2], ah[3], sb + aoff);
                LDSM4(al[0], al[1], al[2], al[3], sb + TILEB + aoff);
                #pragma unroll
                for (int na = 0; na < 4; ++na) {
                    const int np = na >> 1;
                    const int hi = na & 1;  // 0: {r0,r2}, 1: {r1,r3}
                    const uint32_t b0h = bh[np][hi], b1h = bh[np][hi + 2];
                    const uint32_t b0l = bl[np][hi], b1l = bl[np][hi + 2];
                    mma_bf16(acc[ma][na], ah, b0h, b1h);
                    mma_bf16(acc[ma][na], ah, b0l, b1l);
                    mma_bf16(acc[ma][na], al, b0h, b1h);
                }
            }
        }
        __syncthreads();
        if (kit + 2 < NKIT)
            stage_load(sbase + (kit & 1) * STAGE_BYTES, m0, n0, kit + 2, tid);
    }

    // ---- epilogue ----
    const int b = n0 >> 12;
    const int hwbase = n0 & 4095;
    #pragma unroll
    for (int ma = 0; ma < 4; ++ma) {
        const int mrow = warp_m * 64 + ma * 16 + (lane >> 2);
        #pragma unroll
        for (int na = 0; na < 4; ++na) {
            const int nloc = warp_n * 32 + na * 8 + 2 * (lane & 3);
            const float2 inv = *(const float2*)&g_invden[n0 + nloc];
            #pragma unroll
            for (int h = 0; h < 2; ++h) {
                const int co = m0 + mrow + h * 8;
                const float psqr = g_psqr[co];
                float2 o2;
                o2.x = scs_act(acc[ma][na][h * 2 + 0] * inv.x, psqr);
                o2.y = scs_act(acc[ma][na][h * 2 + 1] * inv.y, psqr);
                *(float2*)&out[(((size_t)b * COUT + co) << 12) + hwbase + nloc] = o2;
            }
        }
    }
}

// ---------------- launch ----------------
extern "C" void kernel_launch(void* const* d_in, const int* in_sizes, int n_in,
                              void* d_out, int out_size) {
    const float *x = nullptr, *w = nullptr, *p = nullptr, *q = nullptr;
    for (int i = 0; i < n_in; ++i) {
        const int sz = in_sizes[i];
        if (sz == BB * CIN * HH * WW)      x = (const float*)d_in[i];
        else if (sz == COUT * CIN * 9)     w = (const float*)d_in[i];
        else if (sz == COUT)               p = (const float*)d_in[i];
        else if (sz == 1)                  q = (const float*)d_in[i];
    }
    float* out = (float*)d_out;

    cudaFuncSetAttribute(conv_mma, cudaFuncAttributeMaxDynamicSharedMemorySize,
                         SMEM_TOTAL);

    prep_w<<<COUT, 128>>>(w, p, q);
    prep_split<<<dim3(128, 4, 32), 256>>>(x);
    prep_s<<<NTOT / 256, 256>>>(x);
    prep_invden<<<NTOT / 256, 256>>>(q);

    dim3 grid(2, NTOT / NT);  // M fastest: both M-tiles of an N-tile adjacent (L2 reuse of B)
    conv_mma<<<grid, 256, SMEM_TOTAL>>>(out);
}

// round 9
// speedup vs baseline: 4.6789x; 2.4066x over previous
#include <cuda_runtime.h>
#include <cuda_fp16.h>
#include <cstdint>

// SharpenedCosineSimilarity forward via single-product fp16 mma.sync GEMM with
// implicit im2col (K reordered as k = tap*128 + cin; B tiles staged straight
// from a channel-last fp16 copy of x with cp.async zero-fill halos).
// GEMM view: M=Cout=256, N=B*H*W=131072, K=Cin*9=1152.

#define CIN   128
#define COUT  256
#define HH    64
#define WW    64
#define BB    32
#define KTOT  1152
#define NTOT  (BB*HH*WW)
#define EPSF  1e-12f

#define MT    128
#define NT    128
#define KC    64
#define NKIT  (KTOT/KC)      // 18

#define ROWB  144            // bytes per smem row: 128 data + 16 pad (conflict-free ldmatrix)
#define TILEB (128*ROWB)     // one 128-row tile = 18432 B
#define STAGE_BYTES (2*TILEB) // A|B = 36864 B
#define SMEM_TOTAL  (2*STAGE_BYTES)   // 73728 B

// ---------------- device scratch (static; no allocations) ----------------
__device__ __half g_Ah[COUT * KTOT];           // weights fp16, k = tap*128+cin
__device__ __half g_xh[(size_t)NTOT * CIN];    // channel-last x fp16 (33.5MB)
__device__ float g_psqr[COUT];
__device__ float g_s[NTOT];
__device__ float g_invden[NTOT];

// ---------------- PTX helpers ----------------
static __device__ __forceinline__ uint32_t smem_u32(const void* p) {
    uint32_t a;
    asm("{ .reg .u64 t; cvta.to.shared.u64 t, %1; cvt.u32.u64 %0, t; }" : "=r"(a) : "l"(p));
    return a;
}
#define CP_ASYNC16(s, g) \
    asm volatile("cp.async.cg.shared.global [%0], [%1], 16;" :: "r"(s), "l"(g) : "memory")
#define CP_ASYNC16_Z(s, g, sz) \
    asm volatile("cp.async.cg.shared.global [%0], [%1], 16, %2;" :: "r"(s), "l"(g), "r"(sz) : "memory")
#define CP_COMMIT()  asm volatile("cp.async.commit_group;" ::: "memory")
#define CP_WAIT(n)   asm volatile("cp.async.wait_group %0;" :: "n"(n) : "memory")

#define LDSM4(r0, r1, r2, r3, a) \
    asm volatile("ldmatrix.sync.aligned.m8n8.x4.shared.b16 {%0,%1,%2,%3}, [%4];" \
        : "=r"(r0), "=r"(r1), "=r"(r2), "=r"(r3) : "r"(a))

static __device__ __forceinline__ void mma_f16(float* d, const uint32_t* a,
                                               uint32_t b0, uint32_t b1) {
    asm volatile(
        "mma.sync.aligned.m16n8k16.row.col.f32.f16.f16.f32 "
        "{%0,%1,%2,%3}, {%4,%5,%6,%7}, {%8,%9}, {%0,%1,%2,%3};"
        : "+f"(d[0]), "+f"(d[1]), "+f"(d[2]), "+f"(d[3])
        : "r"(a[0]), "r"(a[1]), "r"(a[2]), "r"(a[3]), "r"(b0), "r"(b1));
}

// ---------------- prep kernels ----------------
__global__ void prep_w(const float* __restrict__ w,
                       const float* __restrict__ p,
                       const float* __restrict__ q) {
    __shared__ float red[4];
    const int co = blockIdx.x;
    const int tid = threadIdx.x;  // 128
    const float* wr = w + co * KTOT;  // layout [Cin][3][3] per cout
    float ssum = 0.f;
    for (int i = tid; i < KTOT; i += 128) { const float v = wr[i]; ssum += v * v; }
    #pragma unroll
    for (int o = 16; o; o >>= 1) ssum += __shfl_xor_sync(0xffffffff, ssum, o);
    if ((tid & 31) == 0) red[tid >> 5] = ssum;
    __syncthreads();
    const float tot = red[0] + red[1] + red[2] + red[3];
    const float qv = q[0] * 0.01f;
    const float qs = qv * qv;
    const float scale = 1.f / (sqrtf(tot) + EPSF + qs);
    for (int i = tid; i < KTOT; i += 128) {
        const int cin = i / 9;
        const int t = i - cin * 9;
        const int k = t * 128 + cin;     // reordered K axis
        g_Ah[co * KTOT + k] = __float2half(wr[i] * scale);
    }
    if (tid == 0) { const float pv = p[co] * 0.1f; g_psqr[co] = pv * pv; }
}

// x[b][cin][h][w] -> xT[b][h][w][cin] fp16. 32x32 tiled transpose.
__global__ void __launch_bounds__(256)
prep_split(const float* __restrict__ x) {
    __shared__ float xs[32][33];
    const int b  = blockIdx.z;
    const int c0 = blockIdx.y * 32;
    const int p0 = blockIdx.x * 32;   // hw tile base
    const int tx = threadIdx.x & 31, ty = threadIdx.x >> 5;  // 32 x 8

    #pragma unroll
    for (int i = 0; i < 4; ++i) {
        const int c = ty + i * 8;
        xs[c][tx] = x[((size_t)b * CIN + c0 + c) * 4096 + p0 + tx];
    }
    __syncthreads();

    const int p  = threadIdx.x >> 3;       // pixel within tile
    const int g4 = (threadIdx.x & 7) * 4;  // cin group of 4
    uint2 hv;
    __half* ph = (__half*)&hv;
    #pragma unroll
    for (int j = 0; j < 4; ++j) ph[j] = __float2half(xs[g4 + j][p]);
    const size_t o = ((size_t)b * 4096 + p0 + p) * CIN + c0 + g4;
    *(uint2*)((char*)g_xh + o * 2) = hv;
}

__global__ void prep_s(const float* __restrict__ x) {
    const int i = blockIdx.x * 256 + threadIdx.x;
    const int b = i >> 12;
    const int hw = i & 4095;
    const float* xp = x + (size_t)b * CIN * 4096 + hw;
    float ssum = 0.f;
    #pragma unroll 8
    for (int c = 0; c < CIN; ++c) { const float v = xp[c * 4096]; ssum += v * v; }
    g_s[i] = ssum;
}

__global__ void prep_invden(const float* __restrict__ q) {
    const int i = blockIdx.x * 256 + threadIdx.x;
    const int b = i >> 12;
    const int hw = i & 4095;
    const int h = hw >> 6, w = hw & 63;
    const float* sp = g_s + b * 4096;
    float acc = 0.f;
    #pragma unroll
    for (int dh = -1; dh <= 1; ++dh) {
        const int hh = h + dh;
        if ((unsigned)hh >= (unsigned)HH) continue;
        #pragma unroll
        for (int dw = -1; dw <= 1; ++dw) {
            const int w2 = w + dw;
            if ((unsigned)w2 >= (unsigned)WW) continue;
            acc += sp[hh * 64 + w2];
        }
    }
    const float qv = q[0] * 0.01f;
    const float qs = qv * qv;
    g_invden[i] = 1.f / (sqrtf(acc + EPSF) + qs);
}

// ---------------- GEMM + fused epilogue ----------------
static __device__ __forceinline__ float scs_act(float y, float psqr) {
    const float sg = __fdividef(1.f, 1.f + __expf(-y));
    const float mag = exp2f(psqr * __log2f(fabsf(y) + EPSF));
    return sg * mag;
}

// Stage one KC=64 chunk: A from reordered weights, B implicitly from xT
// (tap-shifted window, zero-filled halo via cp.async src-size).
static __device__ __forceinline__ void stage_load(uint32_t sb, int m0, int n0,
                                                  int kit, int tid) {
    const int k0 = kit * KC;
    // ---- A: 128 rows x 8 x 16B ----
    #pragma unroll
    for (int rep = 0; rep < 4; ++rep) {
        const int idx = rep * 256 + tid;
        const int c   = idx & 7;
        const int row = idx >> 3;
        const uint32_t sa = sb + row * ROWB + c * 16;
        const char* g = (const char*)g_Ah
                      + ((size_t)(m0 + row) * KTOT + k0) * 2 + c * 16;
        CP_ASYNC16(sa, g);
    }
    // ---- B: implicit im2col from xT, 128 rows x 8 x 16B ----
    const int t    = kit >> 1;          // tap 0..8
    const int cinb = (kit & 1) * 64;    // cin block
    const int dh = t / 3 - 1;
    const int dw = t - (t / 3) * 3 - 1;
    const int b  = n0 >> 12;
    const int h0 = (n0 & 4095) >> 6;    // first of 2 output rows
    #pragma unroll
    for (int rep = 0; rep < 4; ++rep) {
        const int idx = rep * 256 + tid;
        const int c   = idx & 7;
        const int row = idx >> 3;          // pixel within tile
        const uint32_t sa = sb + TILEB + row * ROWB + c * 16;
        const int h = h0 + (row >> 6) + dh;
        const int w = (row & 63) + dw;
        const bool ok = ((unsigned)h < (unsigned)HH) && ((unsigned)w < (unsigned)WW);
        const int hc = ok ? h : 0;
        const int wc = ok ? w : 0;
        const size_t off =
            (((size_t)b * 4096 + hc * 64 + wc) * CIN + cinb + c * 8) * 2;
        const char* g = (const char*)g_xh + off;
        const int sz = ok ? 16 : 0;
        CP_ASYNC16_Z(sa, g, sz);
    }
    CP_COMMIT();
}

__global__ void __launch_bounds__(256, 2)
conv_mma(float* __restrict__ out) {
    extern __shared__ char smem[];
    const uint32_t sbase = smem_u32(smem);
    const int tid = threadIdx.x;
    const int lane = tid & 31;
    const int wid = tid >> 5;
    const int warp_m = wid >> 2;    // 0..1
    const int warp_n = wid & 3;     // 0..3
    const int m0 = blockIdx.x * MT;
    const int n0 = blockIdx.y * NT;

    float acc[4][4][4];
    #pragma unroll
    for (int i = 0; i < 4; ++i)
        #pragma unroll
        for (int j = 0; j < 4; ++j)
            #pragma unroll
            for (int k = 0; k < 4; ++k) acc[i][j][k] = 0.f;

    stage_load(sbase, m0, n0, 0, tid);
    stage_load(sbase + STAGE_BYTES, m0, n0, 1, tid);

    const int lrow = lane & 15;
    const int lkg  = lane >> 4;

    #pragma unroll 1
    for (int kit = 0; kit < NKIT; ++kit) {
        if (kit < NKIT - 2) CP_WAIT(1); else CP_WAIT(0);
        __syncthreads();
        const uint32_t sb = sbase + (kit & 1) * STAGE_BYTES;
        const uint32_t sB = sb + TILEB;

        #pragma unroll
        for (int ks = 0; ks < 4; ++ks) {
            const uint32_t kb = ks * 32 + lkg * 16;
            uint32_t bh[2][4];
            #pragma unroll
            for (int np = 0; np < 2; ++np) {
                const uint32_t boff = (warp_n * 32 + np * 16 + lrow) * ROWB + kb;
                LDSM4(bh[np][0], bh[np][1], bh[np][2], bh[np][3], sB + boff);
            }
            #pragma unroll
            for (int ma = 0; ma < 4; ++ma) {
                const uint32_t aoff = (warp_m * 64 + ma * 16 + lrow) * ROWB + kb;
                uint32_t ah[4];
                LDSM4(ah[0], ah[1], ah[2], ah[3], sb + aoff);
                #pragma unroll
                for (int na = 0; na < 4; ++na) {
                    const int np = na >> 1;
                    const int hi = na & 1;  // 0: {r0,r2}, 1: {r1,r3}
                    mma_f16(acc[ma][na], ah, bh[np][hi], bh[np][hi + 2]);
                }
            }
        }
        __syncthreads();
        if (kit + 2 < NKIT)
            stage_load(sbase + (kit & 1) * STAGE_BYTES, m0, n0, kit + 2, tid);
    }

    // ---- epilogue ----
    const int b = n0 >> 12;
    const int hwbase = n0 & 4095;
    #pragma unroll
    for (int ma = 0; ma < 4; ++ma) {
        const int mrow = warp_m * 64 + ma * 16 + (lane >> 2);
        #pragma unroll
        for (int na = 0; na < 4; ++na) {
            const int nloc = warp_n * 32 + na * 8 + 2 * (lane & 3);
            const float2 inv = *(const float2*)&g_invden[n0 + nloc];
            #pragma unroll
            for (int h = 0; h < 2; ++h) {
                const int co = m0 + mrow + h * 8;
                const float psqr = g_psqr[co];
                float2 o2;
                o2.x = scs_act(acc[ma][na][h * 2 + 0] * inv.x, psqr);
                o2.y = scs_act(acc[ma][na][h * 2 + 1] * inv.y, psqr);
                *(float2*)&out[(((size_t)b * COUT + co) << 12) + hwbase + nloc] = o2;
            }
        }
    }
}

// ---------------- launch ----------------
extern "C" void kernel_launch(void* const* d_in, const int* in_sizes, int n_in,
                              void* d_out, int out_size) {
    const float *x = nullptr, *w = nullptr, *p = nullptr, *q = nullptr;
    for (int i = 0; i < n_in; ++i) {
        const int sz = in_sizes[i];
        if (sz == BB * CIN * HH * WW)      x = (const float*)d_in[i];
        else if (sz == COUT * CIN * 9)     w = (const float*)d_in[i];
        else if (sz == COUT)               p = (const float*)d_in[i];
        else if (sz == 1)                  q = (const float*)d_in[i];
    }
    float* out = (float*)d_out;

    cudaFuncSetAttribute(conv_mma, cudaFuncAttributeMaxDynamicSharedMemorySize,
                         SMEM_TOTAL);

    prep_w<<<COUT, 128>>>(w, p, q);
    prep_split<<<dim3(128, 4, 32), 256>>>(x);
    prep_s<<<NTOT / 256, 256>>>(x);
    prep_invden<<<NTOT / 256, 256>>>(q);

    dim3 grid(2, NTOT / NT);  // M fastest: both M-tiles of an N-tile adjacent (L2 reuse of B)
    conv_mma<<<grid, 256, SMEM_TOTAL>>>(out);
}